// round 16
// baseline (speedup 1.0000x reference)
#include <cuda_runtime.h>
#include <cuda_fp16.h>
#include <mma.h>
#include <math.h>

using namespace nvcuda;

#define TSTEPS 31
#define GBLK 128

// ---------------- scratch ----------------
__device__ __half g_W0h[512 * 2048];
__device__ __half g_W1h[1024 * 2048];
__device__ __half g_Wembh[256 * 2048];
__device__ float g_b0i[2048];
__device__ float g_b1i[2048];
__device__ __half g_convWH[9 * 512 * 256];
__device__ __half g_elwTh[512 * 256];
__device__ __half g_fcTph[1024 * 128];
__device__ float g_fmapT[64 * 256 * 512];
__device__ __half g_fmapTh[64 * 256 * 512];
__device__ float g_efmap[64 * 256 * 256];
__device__ float g_pre[1984 * 2048];
__device__ __half g_xh[2][64 * 1024];
__device__ float g_c0s[64 * 512];
__device__ float g_c1s[64 * 512];
__device__ __half g_h1allh[1984 * 512];
__device__ __half g_gh[1984 * 512];
__device__ float g_eh[1984 * 256];
__device__ unsigned g_barc = 0;
__device__ unsigned g_barg = 0;

__device__ __forceinline__ float tanh_fast(float x) {
    float y; asm("tanh.approx.f32 %0, %1;" : "=f"(y) : "f"(x)); return y;
}
__device__ __forceinline__ float sig_fast(float x) {
    return 0.5f * tanh_fast(0.5f * x) + 0.5f;
}

__device__ __forceinline__ void cp_async16(void* sdst, const void* gsrc, bool ok) {
    unsigned s = (unsigned)__cvta_generic_to_shared(sdst);
    int sz = ok ? 16 : 0;
    asm volatile("cp.async.cg.shared.global [%0], [%1], 16, %2;\n" :: "r"(s), "l"(gsrc), "r"(sz));
}

// grid barrier with scoped atomics (no full membars)
__device__ __forceinline__ void gsync() {
    __syncthreads();
    if (threadIdx.x == 0) {
        unsigned gen = g_barg;
        unsigned old;
        asm volatile("atom.add.acq_rel.gpu.u32 %0, [%1], 1;"
                     : "=r"(old) : "l"(&g_barc) : "memory");
        if (old == GBLK - 1u) {
            g_barc = 0;
            asm volatile("st.release.gpu.u32 [%0], %1;"
                         :: "l"(&g_barg), "r"(gen + 1u) : "memory");
        } else {
            unsigned v;
            do {
                asm volatile("ld.acquire.gpu.u32 %0, [%1];"
                             : "=r"(v) : "l"(&g_barg) : "memory");
            } while (v == gen);
        }
    }
    __syncthreads();
}

// ---------------- setup: tiled weight transposes + small repacks ----------------
__global__ __launch_bounds__(256) void k_wtrans(const float* __restrict__ Whh0,
                                                const float* __restrict__ Wih1,
                                                const float* __restrict__ Whh1,
                                                const float* __restrict__ Wih0,
                                                const float* __restrict__ elw,
                                                const float* __restrict__ fcw,
                                                const float* __restrict__ bih0,
                                                const float* __restrict__ bhh0,
                                                const float* __restrict__ bih1,
                                                const float* __restrict__ bhh1) {
    const int y = blockIdx.y;
    if (y == 3) {   // small repacks (grid-stride)
        const int stride = gridDim.x * blockDim.x;
        const int i0 = blockIdx.x * blockDim.x + threadIdx.x;
        for (int i = i0; i < 2048; i += stride) {
            int col = (i & 3) * 512 + (i >> 2);
            g_b0i[i] = bih0[col] + bhh0[col];
            g_b1i[i] = bih1[col] + bhh1[col];
        }
        for (int i = i0; i < 512 * 256; i += stride) {
            int k = i >> 8, a = i & 255;
            g_elwTh[i] = __float2half(elw[a * 512 + k]);
        }
        for (int i = i0; i < 1024 * 128; i += stride) {
            int k = i >> 7, j = i & 127;
            g_fcTph[i] = __float2half((j < 98) ? fcw[j * 1024 + k] : 0.0f);
        }
        return;
    }
    __shared__ float ts[32][33];
    const int tile = blockIdx.x;
    const int tn = tile & 63, tk = tile >> 6;
    const int kmax = (y == 0) ? 16 : (y == 1) ? 32 : 8;
    if (tk >= kmax) return;
    const int n0 = tn * 32, k0 = tk * 32;
    const int tx = threadIdx.x & 31, ty = threadIdx.x >> 5;
#pragma unroll
    for (int i = 0; i < 4; i++) {
        int nl = ty + i * 8;
        int n = n0 + nl;
        int col = (n & 3) * 512 + (n >> 2);
        int k = k0 + tx;
        float v;
        if (y == 0)      v = Whh0[col * 512 + k];
        else if (y == 1) v = (k < 512) ? Wih1[col * 512 + k] : Whh1[col * 512 + (k - 512)];
        else             v = Wih0[col * 256 + k];
        ts[nl][tx] = v;
    }
    __syncthreads();
    __half* dst = (y == 0) ? g_W0h : (y == 1) ? g_W1h : g_Wembh;
#pragma unroll
    for (int i = 0; i < 4; i++) {
        int kl = ty + i * 8;
        dst[(k0 + kl) * 2048 + n0 + tx] = __float2half(ts[tx][kl]);
    }
}

__global__ __launch_bounds__(256) void k_ctrans(const float* __restrict__ efw) {
    __shared__ float ts[32 * 289];
    const int a0 = blockIdx.x * 32, c0 = blockIdx.y * 32;
    const int tid = threadIdx.x;
    for (int u = tid; u < 32 * 288; u += 256) {
        int al = u / 288, x = u - al * 288;
        ts[al * 289 + x] = efw[(a0 + al) * 4608 + c0 * 9 + x];
    }
    __syncthreads();
    for (int u = tid; u < 9216; u += 256) {
        int al = u & 31, rest = u >> 5;
        int cl = rest & 31, tap = rest >> 5;
        g_convWH[tap * 131072 + (c0 + cl) * 256 + a0 + al] =
            __float2half(ts[al * 289 + cl * 9 + tap]);
    }
}

__global__ __launch_bounds__(256) void k_fmapT(const float* __restrict__ fmap) {
    __shared__ float ts[32][33];
    const int b = blockIdx.y;
    const int tile = blockIdx.x;
    const int tc = (tile & 15) * 32;
    const int th = (tile >> 4) * 32;
    const int tx = threadIdx.x & 31, ty = threadIdx.x >> 5;
    const float* src = fmap + b * 131072;
#pragma unroll
    for (int it = 0; it < 4; it++) {
        int cl = ty + it * 8;
        ts[cl][tx] = src[(tc + cl) * 256 + th + tx];
    }
    __syncthreads();
    float* dst = g_fmapT + b * 131072;
    __half* dsth = g_fmapTh + b * 131072;
#pragma unroll
    for (int it = 0; it < 4; it++) {
        int hwl = ty + it * 8;
        float v = ts[tx][hwl];
        dst[(th + hwl) * 512 + tc + tx] = v;
        dsth[(th + hwl) * 512 + tc + tx] = __float2half(v);
    }
}

// states only
__global__ void k_init2(const float* __restrict__ h0, const float* __restrict__ c0) {
    int r = blockIdx.x * blockDim.x + threadIdx.x;
    if (r < 32768) {
        int b = r >> 9, d = r & 511;
        g_xh[1][b * 1024 + d] = __float2half(h0[r]);
    } else if (r < 65536) {
        int q = r - 32768; int b = q >> 9, d = q & 511;
        g_xh[0][b * 1024 + 512 + d] = __float2half(h0[32768 + q]);
    } else if (r < 98304) {
        g_c0s[r - 65536] = c0[r - 65536];
    } else if (r < 131072) {
        g_c1s[r - 98304] = c0[32768 + (r - 98304)];
    }
}

// ---------------- pre-embedding GEMM: g_pre = E @ Wemb (fp16, E gathered on the fly) ----------------
__global__ __launch_bounds__(256) void k_preemb(const float* __restrict__ emb,
                                                const int* __restrict__ target) {
    __shared__ __half As[64 * 72];
    __shared__ __half Bs[64 * 136];
    const int tid = threadIdx.x;
    const int warp = tid >> 5;
    const int wm = warp >> 2, wn = warp & 3;
    const int n0 = blockIdx.x * 128;
    const int t = blockIdx.y;                 // m0 = t*64, rows are batches
    wmma::fragment<wmma::accumulator, 16, 16, 16, float> acc[2][2];
#pragma unroll
    for (int i = 0; i < 2; i++)
#pragma unroll
        for (int j = 0; j < 2; j++) wmma::fill_fragment(acc[i][j], 0.0f);
    for (int kt = 0; kt < 256; kt += 64) {
#pragma unroll
        for (int j = 0; j < 2; j++) {
            int u = tid + j * 256;
            int row = u >> 3, seg = u & 7;    // row = batch
            int lab = (t == 0) ? 0 : target[row * 30 + t - 1];
            const float* src = emb + lab * 256 + kt + seg * 8;
            float4 a4 = *(const float4*)src;
            float4 b4 = *(const float4*)(src + 4);
            __half2 p0 = __floats2half2_rn(a4.x, a4.y);
            __half2 p1 = __floats2half2_rn(a4.z, a4.w);
            __half2 p2 = __floats2half2_rn(b4.x, b4.y);
            __half2 p3 = __floats2half2_rn(b4.z, b4.w);
            uint4 v = make_uint4(*(unsigned*)&p0, *(unsigned*)&p1,
                                 *(unsigned*)&p2, *(unsigned*)&p3);
            *(uint4*)&As[row * 72 + seg * 8] = v;
        }
#pragma unroll
        for (int j = 0; j < 4; j++) {
            int u = tid + j * 256;
            int row = u >> 4, seg = u & 15;
            *(uint4*)&Bs[row * 136 + seg * 8] =
                *(const uint4*)(g_Wembh + (kt + row) * 2048 + n0 + seg * 8);
        }
        __syncthreads();
#pragma unroll
        for (int kf = 0; kf < 4; kf++) {
            wmma::fragment<wmma::matrix_a, 16, 16, 16, __half, wmma::row_major> af[2];
            wmma::fragment<wmma::matrix_b, 16, 16, 16, __half, wmma::row_major> bf[2];
#pragma unroll
            for (int i = 0; i < 2; i++)
                wmma::load_matrix_sync(af[i], &As[(wm * 32 + i * 16) * 72 + kf * 16], 72);
#pragma unroll
            for (int j = 0; j < 2; j++)
                wmma::load_matrix_sync(bf[j], &Bs[(kf * 16) * 136 + wn * 32 + j * 16], 136);
#pragma unroll
            for (int i = 0; i < 2; i++)
#pragma unroll
                for (int j = 0; j < 2; j++)
                    wmma::mma_sync(acc[i][j], af[i], bf[j], acc[i][j]);
        }
        __syncthreads();
    }
#pragma unroll
    for (int i = 0; i < 2; i++)
#pragma unroll
        for (int j = 0; j < 2; j++)
            wmma::store_matrix_sync(g_pre + (t * 64 + wm * 32 + i * 16) * 2048 + n0 + wn * 32 + j * 16,
                                    acc[i][j], 2048, wmma::mem_row_major);
}

// ---------------- conv v5: fp16, M256xN128 tile, cp.async double-buffer ----------------
#define CONV_BUF 27136
__global__ __launch_bounds__(256) void k_conv() {
    extern __shared__ __half csm[];
    const int tid = threadIdx.x;
    const int warp = tid >> 5;
    const int wm = warp >> 1, wn = warp & 1;
    const int n0 = blockIdx.x * 128;
    const int b = blockIdx.y;
    const __half* fTh = g_fmapTh + b * 131072;

    wmma::fragment<wmma::accumulator, 16, 16, 16, float> acc[4][4];
#pragma unroll
    for (int i = 0; i < 4; i++)
#pragma unroll
        for (int j = 0; j < 4; j++) wmma::fill_fragment(acc[i][j], 0.0f);

    auto issue = [&](int q) {
        int tap = q >> 3, cch = q & 7;
        int dy = tap / 3 - 1, dx = tap % 3 - 1;
        __half* A = csm + (q & 1) * CONV_BUF;
        __half* B = A + 18432;
#pragma unroll
        for (int j = 0; j < 8; j++) {
            int u = tid + j * 256;
            int row = u >> 3, seg = u & 7;
            int yy = (row >> 5) + dy, xx = (row & 31) + dx;
            bool ok = (yy >= 0) && (yy < 8) && (xx >= 0) && (xx < 32);
            const __half* src = ok ? (fTh + (yy * 32 + xx) * 512 + cch * 64 + seg * 8) : fTh;
            cp_async16(A + row * 72 + seg * 8, src, ok);
        }
        const __half* bsrc = g_convWH + (tap * 512 + cch * 64) * 256 + n0;
#pragma unroll
        for (int j = 0; j < 4; j++) {
            int u = tid + j * 256;
            int row = u >> 4, c16 = u & 15;
            cp_async16(B + row * 136 + c16 * 8, bsrc + row * 256 + c16 * 8, true);
        }
        asm volatile("cp.async.commit_group;\n" ::: "memory");
    };

    issue(0);
#pragma unroll 1
    for (int q = 0; q < 72; q++) {
        if (q < 71) {
            issue(q + 1);
            asm volatile("cp.async.wait_group 1;\n" ::: "memory");
        } else {
            asm volatile("cp.async.wait_group 0;\n" ::: "memory");
        }
        __syncthreads();
        const __half* A = csm + (q & 1) * CONV_BUF;
        const __half* B = A + 18432;
#pragma unroll
        for (int kf = 0; kf < 4; kf++) {
            wmma::fragment<wmma::matrix_a, 16, 16, 16, __half, wmma::row_major> af[4];
#pragma unroll
            for (int i = 0; i < 4; i++)
                wmma::load_matrix_sync(af[i], &A[(wm * 64 + i * 16) * 72 + kf * 16], 72);
#pragma unroll
            for (int j = 0; j < 4; j++) {
                wmma::fragment<wmma::matrix_b, 16, 16, 16, __half, wmma::row_major> bf;
                wmma::load_matrix_sync(bf, &B[(kf * 16) * 136 + wn * 64 + j * 16], 136);
#pragma unroll
                for (int i = 0; i < 4; i++)
                    wmma::mma_sync(acc[i][j], af[i], bf, acc[i][j]);
            }
        }
        __syncthreads();
    }
    float* eb = g_efmap + b * 65536;
#pragma unroll
    for (int i = 0; i < 4; i++)
#pragma unroll
        for (int j = 0; j < 4; j++)
            wmma::store_matrix_sync(eb + (n0 + wn * 64 + j * 16) * 256 + wm * 64 + i * 16,
                                    acc[i][j], 256, wmma::mem_col_major);
}

// ---------------- persistent recurrence (R15 version, cheap gsync) ----------------
__global__ __launch_bounds__(256)
void k_steps() {
    extern __shared__ char smc[];
    __half* Ah  = (__half*)smc;
    __half* W0s = (__half*)(smc + 132096);
    __half* W1s = (__half*)(smc + 132096 + 24576);
    float*  Cs  = (float*)(smc + 132096 + 24576 + 49152);
    const int tid = threadIdx.x;
    const int bid = blockIdx.x;
    const int warp = tid >> 5;
    const int mt = warp & 3, kh = warp >> 2;
    const int n0 = bid * 16;

    for (int j = 0; j < 4; j++) {
        int u = tid + j * 256;
        int k = u >> 1, s = u & 1;
        *(uint4*)&W0s[k * 24 + s * 8] = *(const uint4*)(g_W0h + k * 2048 + n0 + s * 8);
    }
    for (int j = 0; j < 8; j++) {
        int u = tid + j * 256;
        int k = u >> 1, s = u & 1;
        *(uint4*)&W1s[k * 24 + s * 8] = *(const uint4*)(g_W1h + k * 2048 + n0 + s * 8);
    }
    __syncthreads();

    const int pb = tid >> 2, pdl = tid & 3;
    const int pr = pb & 15, pmt = pb >> 4;
    const int pd = bid * 4 + pdl;
    const float4 bi0 = *(const float4*)&g_b0i[n0 + pdl * 4];
    const float4 bi1 = *(const float4*)&g_b1i[n0 + pdl * 4];

#pragma unroll 1
    for (int k = 0; k <= TSTEPS; k++) {
        const int rb = (k + 1) & 1, wb = k & 1;

        {
            const __half* Ag = g_xh[rb];
#pragma unroll
            for (int j = 0; j < 32; j++) {
                int u = tid + j * 256;
                int row = u >> 7, seg = u & 127;
                *(uint4*)&Ah[row * 1032 + seg * 8] =
                    __ldcg((const uint4*)(Ag + row * 1024 + seg * 8));
            }
        }
        float4 pe;
        float c0v = 0.f, c1v = 0.f;
        if (k < TSTEPS) {
            pe = *(const float4*)&g_pre[(k * 64 + pb) * 2048 + n0 + pdl * 4];
            c0v = g_c0s[pb * 512 + pd];
        }
        if (k > 0) c1v = g_c1s[pb * 512 + pd];
        __syncthreads();

        if (k < TSTEPS) {
            wmma::fragment<wmma::accumulator, 16, 16, 16, float> a0, a1;
            wmma::fill_fragment(a0, 0.0f);
            wmma::fill_fragment(a1, 0.0f);
#pragma unroll
            for (int q = 0; q < 16; q++) {
                int kf = kh * 16 + q;
                wmma::fragment<wmma::matrix_a, 16, 16, 16, __half, wmma::row_major> af;
                wmma::fragment<wmma::matrix_b, 16, 16, 16, __half, wmma::row_major> bf;
                wmma::load_matrix_sync(af, &Ah[(mt * 16) * 1032 + kf * 16], 1032);
                wmma::load_matrix_sync(bf, &W0s[(kf * 16) * 24], 24);
                if (q & 1) wmma::mma_sync(a1, af, bf, a1);
                else       wmma::mma_sync(a0, af, bf, a0);
            }
#pragma unroll
            for (int i = 0; i < a0.num_elements; i++) a0.x[i] += a1.x[i];
            wmma::store_matrix_sync(&Cs[warp * 256], a0, 16, wmma::mem_row_major);
        }
        if (k > 0) {
            wmma::fragment<wmma::accumulator, 16, 16, 16, float> a0, a1;
            wmma::fill_fragment(a0, 0.0f);
            wmma::fill_fragment(a1, 0.0f);
#pragma unroll
            for (int q = 0; q < 32; q++) {
                int kf = kh * 32 + q;
                wmma::fragment<wmma::matrix_a, 16, 16, 16, __half, wmma::row_major> af;
                wmma::fragment<wmma::matrix_b, 16, 16, 16, __half, wmma::row_major> bf;
                wmma::load_matrix_sync(af, &Ah[(mt * 16) * 1032 + kf * 16], 1032);
                wmma::load_matrix_sync(bf, &W1s[(kf * 16) * 24], 24);
                if (q & 1) wmma::mma_sync(a1, af, bf, a1);
                else       wmma::mma_sync(a0, af, bf, a0);
            }
#pragma unroll
            for (int i = 0; i < a0.num_elements; i++) a0.x[i] += a1.x[i];
            wmma::store_matrix_sync(&Cs[2048 + warp * 256], a0, 16, wmma::mem_row_major);
        }
        __syncthreads();

        if (k < TSTEPS) {
            int base = pmt * 256 + pr * 16 + pdl * 4;
            float gi = Cs[base + 0] + Cs[1024 + base + 0] + pe.x + bi0.x;
            float gf = Cs[base + 1] + Cs[1024 + base + 1] + pe.y + bi0.y;
            float gg = Cs[base + 2] + Cs[1024 + base + 2] + pe.z + bi0.z;
            float go = Cs[base + 3] + Cs[1024 + base + 3] + pe.w + bi0.w;
            float c = sig_fast(gf) * c0v + sig_fast(gi) * tanh_fast(gg);
            float h = sig_fast(go) * tanh_fast(c);
            g_c0s[pb * 512 + pd] = c;
            g_xh[wb][pb * 1024 + pd] = __float2half(h);
        }
        if (k > 0) {
            int base = 2048 + pmt * 256 + pr * 16 + pdl * 4;
            float gi = Cs[base + 0] + Cs[1024 + base + 0] + bi1.x;
            float gf = Cs[base + 1] + Cs[1024 + base + 1] + bi1.y;
            float gg = Cs[base + 2] + Cs[1024 + base + 2] + bi1.z;
            float go = Cs[base + 3] + Cs[1024 + base + 3] + bi1.w;
            float c = sig_fast(gf) * c1v + sig_fast(gi) * tanh_fast(gg);
            float h = sig_fast(go) * tanh_fast(c);
            g_c1s[pb * 512 + pd] = c;
            __half hh = __float2half(h);
            g_xh[wb][pb * 1024 + 512 + pd] = hh;
            g_h1allh[((k - 1) * 64 + pb) * 512 + pd] = hh;
        }
        if (k < TSTEPS) gsync();
    }
}

// ---------------- epilogue: e_h = h1all @ elwT (fp16) ----------------
__global__ __launch_bounds__(256) void k_eh() {
    __shared__ __half As[64 * 72];
    __shared__ __half Bs[64 * 136];
    const int tid = threadIdx.x;
    const int warp = tid >> 5;
    const int wm = warp >> 2, wn = warp & 3;
    const int n0 = blockIdx.x * 128, m0 = blockIdx.y * 64;
    wmma::fragment<wmma::accumulator, 16, 16, 16, float> acc[2][2];
#pragma unroll
    for (int i = 0; i < 2; i++)
#pragma unroll
        for (int j = 0; j < 2; j++) wmma::fill_fragment(acc[i][j], 0.0f);
    for (int kt = 0; kt < 512; kt += 64) {
#pragma unroll
        for (int j = 0; j < 2; j++) {
            int u = tid + j * 256;
            int row = u >> 3, seg = u & 7;
            *(uint4*)&As[row * 72 + seg * 8] =
                *(const uint4*)(g_h1allh + (m0 + row) * 512 + kt + seg * 8);
        }
#pragma unroll
        for (int j = 0; j < 4; j++) {
            int u = tid + j * 256;
            int row = u >> 4, seg = u & 15;
            *(uint4*)&Bs[row * 136 + seg * 8] =
                *(const uint4*)(g_elwTh + (kt + row) * 256 + n0 + seg * 8);
        }
        __syncthreads();
#pragma unroll
        for (int kf = 0; kf < 4; kf++) {
            wmma::fragment<wmma::matrix_a, 16, 16, 16, __half, wmma::row_major> af[2];
            wmma::fragment<wmma::matrix_b, 16, 16, 16, __half, wmma::row_major> bf[2];
#pragma unroll
            for (int i = 0; i < 2; i++)
                wmma::load_matrix_sync(af[i], &As[(wm * 32 + i * 16) * 72 + kf * 16], 72);
#pragma unroll
            for (int j = 0; j < 2; j++)
                wmma::load_matrix_sync(bf[j], &Bs[(kf * 16) * 136 + wn * 32 + j * 16], 136);
#pragma unroll
            for (int i = 0; i < 2; i++)
#pragma unroll
                for (int j = 0; j < 2; j++)
                    wmma::mma_sync(acc[i][j], af[i], bf[j], acc[i][j]);
        }
        __syncthreads();
    }
#pragma unroll
    for (int i = 0; i < 2; i++)
#pragma unroll
        for (int j = 0; j < 2; j++)
            wmma::store_matrix_sync(g_eh + (m0 + wm * 32 + i * 16) * 256 + n0 + wn * 32 + j * 16,
                                    acc[i][j], 256, wmma::mem_row_major);
}

// ---------------- epilogue: scores + softmax (8 timesteps per block) ----------------
__global__ __launch_bounds__(256) void k_scores(const float* __restrict__ elb,
                                                const float* __restrict__ efb,
                                                const float* __restrict__ aw,
                                                const float* __restrict__ ab,
                                                float* __restrict__ out) {
    const int tg = blockIdx.x, b = blockIdx.y;
    const int nt = (tg < 3) ? 8 : 7;
    const int tid = threadIdx.x;
    __shared__ float ehs[8 * 256], aws[256];
    __shared__ float red[8], fin;
    const float bias = elb[tid] + efb[tid];
    for (int j = 0; j < 8; j++)
        ehs[j * 256 + tid] = (j < nt) ? g_eh[((tg * 8 + j) * 64 + b) * 256 + tid] + bias : 0.0f;
    aws[tid] = aw[tid];
    __syncthreads();

    float sc[8];
#pragma unroll
    for (int j = 0; j < 8; j++) sc[j] = ab[0];
    const float* ef = g_efmap + b * 65536 + tid;
#pragma unroll 2
    for (int a = 0; a < 256; a++) {
        float e = ef[a * 256];
        float w = aws[a];
#pragma unroll
        for (int j = 0; j < 8; j++)
            sc[j] += w * tanh_fast(ehs[j * 256 + a] + e);
    }

    const int wp = tid >> 5, lane = tid & 31;
    for (int j = 0; j < nt; j++) {
        float m = sc[j];
#pragma unroll
        for (int o = 16; o; o >>= 1) m = fmaxf(m, __shfl_xor_sync(0xffffffffu, m, o));
        if (lane == 0) red[wp] = m;
        __syncthreads();
        if (tid == 0) {
            float v = red[0];
#pragma unroll
            for (int i = 1; i < 8; i++) v = fmaxf(v, red[i]);
            fin = v;
        }
        __syncthreads();
        float e = expf(sc[j] - fin);
        float s = e;
#pragma unroll
        for (int o = 16; o; o >>= 1) s += __shfl_xor_sync(0xffffffffu, s, o);
        if (lane == 0) red[wp] = s;
        __syncthreads();
        if (tid == 0) {
            float v = 0;
#pragma unroll
            for (int i = 0; i < 8; i++) v += red[i];
            fin = v;
        }
        __syncthreads();
        out[194432 + (b * 31 + tg * 8 + j) * 256 + tid] = e / fin;
        __syncthreads();
    }
}

// ---------------- epilogue: glimpse (exact fp32, 256 thr x 2 ch) ----------------
__global__ __launch_bounds__(256) void k_glimpse(float* __restrict__ out) {
    __shared__ float ms[16 * 256];
    const int th = blockIdx.x, b = blockIdx.y;
    const int tid = threadIdx.x;
    const int nt = (th == 0) ? 16 : 15;
    for (int i = tid; i < 16 * 256; i += 256) {
        int tt = i >> 8;
        ms[i] = (tt < nt) ? out[194432 + (b * 31 + th * 16 + tt) * 256 + (i & 255)] : 0.0f;
    }
    __syncthreads();
    const int c = tid * 2;
    float2 acc[16];
#pragma unroll
    for (int tt = 0; tt < 16; tt++) acc[tt] = make_float2(0.f, 0.f);
    const float* fp = g_fmapT + b * 131072 + c;
#pragma unroll 4
    for (int hw = 0; hw < 256; hw++) {
        float2 f = *(const float2*)(fp + hw * 512);
#pragma unroll
        for (int tt = 0; tt < 16; tt++) {
            float m = ms[tt * 256 + hw];
            acc[tt].x += f.x * m; acc[tt].y += f.y * m;
        }
    }
#pragma unroll
    for (int tt = 0; tt < 16; tt++)
        if (tt < nt) {
            int row = b * 31 + th * 16 + tt;
            *(float2*)&out[702336 + row * 512 + c] = acc[tt];
            *(__half2*)&g_gh[row * 512 + c] = __floats2half2_rn(acc[tt].x, acc[tt].y);
        }
}

// ---------------- epilogue: fc logits (fp16) ----------------
__global__ __launch_bounds__(256) void k_fc(const float* __restrict__ fcb,
                                            float* __restrict__ out) {
    __shared__ __half As[64 * 72];
    __shared__ __half Bs[64 * 136];
    __shared__ float Cs[64 * 128];
    const int t = blockIdx.x;
    const int tid = threadIdx.x;
    const int warp = tid >> 5;
    const int wm = warp >> 2, wn = warp & 3;
    wmma::fragment<wmma::accumulator, 16, 16, 16, float> acc[2][2];
#pragma unroll
    for (int i = 0; i < 2; i++)
#pragma unroll
        for (int j = 0; j < 2; j++) wmma::fill_fragment(acc[i][j], 0.0f);
    for (int kt = 0; kt < 1024; kt += 64) {
#pragma unroll
        for (int j = 0; j < 2; j++) {
            int u = tid + j * 256;
            int row = u >> 3, seg = u & 7;
            const __half* src = (kt < 512)
                ? (g_h1allh + (t * 64 + row) * 512 + kt + seg * 8)
                : (g_gh + (row * 31 + t) * 512 + (kt - 512) + seg * 8);
            *(uint4*)&As[row * 72 + seg * 8] = *(const uint4*)src;
        }
#pragma unroll
        for (int j = 0; j < 4; j++) {
            int u = tid + j * 256;
            int row = u >> 4, seg = u & 15;
            *(uint4*)&Bs[row * 136 + seg * 8] =
                *(const uint4*)(g_fcTph + (kt + row) * 128 + seg * 8);
        }
        __syncthreads();
#pragma unroll
        for (int kf = 0; kf < 4; kf++) {
            wmma::fragment<wmma::matrix_a, 16, 16, 16, __half, wmma::row_major> af[2];
            wmma::fragment<wmma::matrix_b, 16, 16, 16, __half, wmma::row_major> bf[2];
#pragma unroll
            for (int i = 0; i < 2; i++)
                wmma::load_matrix_sync(af[i], &As[(wm * 32 + i * 16) * 72 + kf * 16], 72);
#pragma unroll
            for (int j = 0; j < 2; j++)
                wmma::load_matrix_sync(bf[j], &Bs[(kf * 16) * 136 + wn * 32 + j * 16], 136);
#pragma unroll
            for (int i = 0; i < 2; i++)
#pragma unroll
                for (int j = 0; j < 2; j++)
                    wmma::mma_sync(acc[i][j], af[i], bf[j], acc[i][j]);
        }
        __syncthreads();
    }
#pragma unroll
    for (int i = 0; i < 2; i++)
#pragma unroll
        for (int j = 0; j < 2; j++)
            wmma::store_matrix_sync(&Cs[(wm * 32 + i * 16) * 128 + wn * 32 + j * 16],
                                    acc[i][j], 128, wmma::mem_row_major);
    __syncthreads();
    for (int i = tid; i < 64 * 98; i += 256) {
        int m = i / 98, j = i % 98;
        out[(m * 31 + t) * 98 + j] = Cs[m * 128 + j] + fcb[j];
    }
}

// ---------------- launch (fork conv branch onto a second stream) ----------------
extern "C" void kernel_launch(void* const* d_in, const int* in_sizes, int n_in,
                              void* d_out, int out_size) {
    const float* fmap   = (const float*)d_in[0];
    const float* h0     = (const float*)d_in[1];
    const float* c0     = (const float*)d_in[2];
    const int*   target = (const int*)d_in[3];
    const float* emb    = (const float*)d_in[5];
    const float* Wih0   = (const float*)d_in[6];
    const float* Whh0   = (const float*)d_in[7];
    const float* bih0   = (const float*)d_in[8];
    const float* bhh0   = (const float*)d_in[9];
    const float* Wih1   = (const float*)d_in[10];
    const float* Whh1   = (const float*)d_in[11];
    const float* bih1   = (const float*)d_in[12];
    const float* bhh1   = (const float*)d_in[13];
    const float* elw    = (const float*)d_in[14];
    const float* elb    = (const float*)d_in[15];
    const float* efw    = (const float*)d_in[16];
    const float* efb    = (const float*)d_in[17];
    const float* aw     = (const float*)d_in[18];
    const float* ab     = (const float*)d_in[19];
    const float* fcw    = (const float*)d_in[20];
    const float* fcb    = (const float*)d_in[21];
    float* out = (float*)d_out;

    const int SMEM_STEPS = 132096 + 24576 + 49152 + 16384;  // 222208
    const int SMEM_CONV  = 2 * CONV_BUF * 2;                // 108544

    static cudaStream_t s2 = nullptr;
    static cudaEvent_t evRoot = nullptr, evConv = nullptr;
    if (!s2) {
        cudaFuncSetAttribute(k_steps, cudaFuncAttributeMaxDynamicSharedMemorySize, SMEM_STEPS);
        cudaFuncSetAttribute(k_conv, cudaFuncAttributeMaxDynamicSharedMemorySize, SMEM_CONV);
        cudaStreamCreateWithFlags(&s2, cudaStreamNonBlocking);
        cudaEventCreateWithFlags(&evRoot, cudaEventDisableTiming);
        cudaEventCreateWithFlags(&evConv, cudaEventDisableTiming);
    }

    cudaEventRecord(evRoot, 0);
    cudaStreamWaitEvent(s2, evRoot, 0);
    k_fmapT<<<dim3(128, 64), 256, 0, s2>>>(fmap);
    k_ctrans<<<dim3(8, 16), 256, 0, s2>>>(efw);
    k_conv<<<dim3(2, 64), 256, SMEM_CONV, s2>>>();
    cudaEventRecord(evConv, s2);

    k_wtrans<<<dim3(2048, 4), 256>>>(Whh0, Wih1, Whh1, Wih0, elw, fcw,
                                     bih0, bhh0, bih1, bhh1);
    k_init2<<<512, 256>>>(h0, c0);
    k_preemb<<<dim3(16, 31), 256>>>(emb, target);
    k_steps<<<GBLK, 256, SMEM_STEPS>>>();
    k_eh<<<dim3(2, 31), 256>>>();

    cudaStreamWaitEvent(0, evConv, 0);
    k_scores<<<dim3(4, 64), 256>>>(elb, efb, aw, ab, out);
    k_glimpse<<<dim3(2, 64), 256>>>(out);
    k_fc<<<31, 256>>>(fcb, out);
}

// round 17
// speedup vs baseline: 1.0409x; 1.0409x over previous
#include <cuda_runtime.h>
#include <cuda_fp16.h>
#include <mma.h>
#include <math.h>

using namespace nvcuda;

#define TSTEPS 31
#define GBLK 128

// ---------------- scratch ----------------
__device__ __half g_W0h[512 * 2048];
__device__ __half g_W1h[1024 * 2048];
__device__ __half g_Wembh[256 * 2048];
__device__ float g_b0i[2048];
__device__ float g_b1i[2048];
__device__ __half g_convWH[9 * 512 * 256];
__device__ __half g_elwTh[512 * 256];
__device__ __half g_fcTph[1024 * 128];
__device__ float g_fmapT[64 * 256 * 512];
__device__ __half g_fmapTh[64 * 256 * 512];
__device__ float g_efmap[64 * 256 * 256];
__device__ float g_pre[1984 * 2048];
__device__ __half g_xh[2][64 * 1024];
__device__ float g_c0s[64 * 512];
__device__ float g_c1s[64 * 512];
__device__ __half g_h1allh[1984 * 512];
__device__ __half g_gh[1984 * 512];
__device__ float g_eh[1984 * 256];
__device__ unsigned g_barc = 0;
__device__ unsigned g_barg = 0;

__device__ __forceinline__ float tanh_fast(float x) {
    float y; asm("tanh.approx.f32 %0, %1;" : "=f"(y) : "f"(x)); return y;
}
__device__ __forceinline__ float sig_fast(float x) {
    return 0.5f * tanh_fast(0.5f * x) + 0.5f;
}

__device__ __forceinline__ void cp_async16(void* sdst, const void* gsrc, bool ok) {
    unsigned s = (unsigned)__cvta_generic_to_shared(sdst);
    int sz = ok ? 16 : 0;
    asm volatile("cp.async.cg.shared.global [%0], [%1], 16, %2;\n" :: "r"(s), "l"(gsrc), "r"(sz));
}

__device__ __forceinline__ void gsync() {
    __syncthreads();
    if (threadIdx.x == 0) {
        unsigned gen = g_barg;
        unsigned old;
        asm volatile("atom.add.acq_rel.gpu.u32 %0, [%1], 1;"
                     : "=r"(old) : "l"(&g_barc) : "memory");
        if (old == GBLK - 1u) {
            g_barc = 0;
            asm volatile("st.release.gpu.u32 [%0], %1;"
                         :: "l"(&g_barg), "r"(gen + 1u) : "memory");
        } else {
            unsigned v;
            do {
                asm volatile("ld.acquire.gpu.u32 %0, [%1];"
                             : "=r"(v) : "l"(&g_barg) : "memory");
            } while (v == gen);
        }
    }
    __syncthreads();
}

// ---------------- setup: tiled weight transposes + small repacks ----------------
__global__ __launch_bounds__(256) void k_wtrans(const float* __restrict__ Whh0,
                                                const float* __restrict__ Wih1,
                                                const float* __restrict__ Whh1,
                                                const float* __restrict__ Wih0,
                                                const float* __restrict__ elw,
                                                const float* __restrict__ fcw,
                                                const float* __restrict__ bih0,
                                                const float* __restrict__ bhh0,
                                                const float* __restrict__ bih1,
                                                const float* __restrict__ bhh1) {
    const int y = blockIdx.y;
    if (y == 3) {
        const int stride = gridDim.x * blockDim.x;
        const int i0 = blockIdx.x * blockDim.x + threadIdx.x;
        for (int i = i0; i < 2048; i += stride) {
            int col = (i & 3) * 512 + (i >> 2);
            g_b0i[i] = bih0[col] + bhh0[col];
            g_b1i[i] = bih1[col] + bhh1[col];
        }
        for (int i = i0; i < 512 * 256; i += stride) {
            int k = i >> 8, a = i & 255;
            g_elwTh[i] = __float2half(elw[a * 512 + k]);
        }
        for (int i = i0; i < 1024 * 128; i += stride) {
            int k = i >> 7, j = i & 127;
            g_fcTph[i] = __float2half((j < 98) ? fcw[j * 1024 + k] : 0.0f);
        }
        return;
    }
    __shared__ float ts[32][33];
    const int tile = blockIdx.x;
    const int tn = tile & 63, tk = tile >> 6;
    const int kmax = (y == 0) ? 16 : (y == 1) ? 32 : 8;
    if (tk >= kmax) return;
    const int n0 = tn * 32, k0 = tk * 32;
    const int tx = threadIdx.x & 31, ty = threadIdx.x >> 5;
#pragma unroll
    for (int i = 0; i < 4; i++) {
        int nl = ty + i * 8;
        int n = n0 + nl;
        int col = (n & 3) * 512 + (n >> 2);
        int k = k0 + tx;
        float v;
        if (y == 0)      v = Whh0[col * 512 + k];
        else if (y == 1) v = (k < 512) ? Wih1[col * 512 + k] : Whh1[col * 512 + (k - 512)];
        else             v = Wih0[col * 256 + k];
        ts[nl][tx] = v;
    }
    __syncthreads();
    __half* dst = (y == 0) ? g_W0h : (y == 1) ? g_W1h : g_Wembh;
#pragma unroll
    for (int i = 0; i < 4; i++) {
        int kl = ty + i * 8;
        dst[(k0 + kl) * 2048 + n0 + tx] = __float2half(ts[tx][kl]);
    }
}

__global__ __launch_bounds__(256) void k_ctrans(const float* __restrict__ efw) {
    __shared__ float ts[32 * 289];
    const int a0 = blockIdx.x * 32, c0 = blockIdx.y * 32;
    const int tid = threadIdx.x;
    for (int u = tid; u < 32 * 288; u += 256) {
        int al = u / 288, x = u - al * 288;
        ts[al * 289 + x] = efw[(a0 + al) * 4608 + c0 * 9 + x];
    }
    __syncthreads();
    for (int u = tid; u < 9216; u += 256) {
        int al = u & 31, rest = u >> 5;
        int cl = rest & 31, tap = rest >> 5;
        g_convWH[tap * 131072 + (c0 + cl) * 256 + a0 + al] =
            __float2half(ts[al * 289 + cl * 9 + tap]);
    }
}

__global__ __launch_bounds__(256) void k_fmapT(const float* __restrict__ fmap) {
    __shared__ float ts[32][33];
    const int b = blockIdx.y;
    const int tile = blockIdx.x;
    const int tc = (tile & 15) * 32;
    const int th = (tile >> 4) * 32;
    const int tx = threadIdx.x & 31, ty = threadIdx.x >> 5;
    const float* src = fmap + b * 131072;
#pragma unroll
    for (int it = 0; it < 4; it++) {
        int cl = ty + it * 8;
        ts[cl][tx] = src[(tc + cl) * 256 + th + tx];
    }
    __syncthreads();
    float* dst = g_fmapT + b * 131072;
    __half* dsth = g_fmapTh + b * 131072;
#pragma unroll
    for (int it = 0; it < 4; it++) {
        int hwl = ty + it * 8;
        float v = ts[tx][hwl];
        dst[(th + hwl) * 512 + tc + tx] = v;
        dsth[(th + hwl) * 512 + tc + tx] = __float2half(v);
    }
}

__global__ void k_init2(const float* __restrict__ h0, const float* __restrict__ c0) {
    int r = blockIdx.x * blockDim.x + threadIdx.x;
    if (r < 32768) {
        int b = r >> 9, d = r & 511;
        g_xh[1][b * 1024 + d] = __float2half(h0[r]);
    } else if (r < 65536) {
        int q = r - 32768; int b = q >> 9, d = q & 511;
        g_xh[0][b * 1024 + 512 + d] = __float2half(h0[32768 + q]);
    } else if (r < 98304) {
        g_c0s[r - 65536] = c0[r - 65536];
    } else if (r < 131072) {
        g_c1s[r - 98304] = c0[32768 + (r - 98304)];
    }
}

// ---------------- pre-embedding GEMM ----------------
__global__ __launch_bounds__(256) void k_preemb(const float* __restrict__ emb,
                                                const int* __restrict__ target) {
    __shared__ __half As[64 * 72];
    __shared__ __half Bs[64 * 136];
    const int tid = threadIdx.x;
    const int warp = tid >> 5;
    const int wm = warp >> 2, wn = warp & 3;
    const int n0 = blockIdx.x * 128;
    const int t = blockIdx.y;
    wmma::fragment<wmma::accumulator, 16, 16, 16, float> acc[2][2];
#pragma unroll
    for (int i = 0; i < 2; i++)
#pragma unroll
        for (int j = 0; j < 2; j++) wmma::fill_fragment(acc[i][j], 0.0f);
    for (int kt = 0; kt < 256; kt += 64) {
#pragma unroll
        for (int j = 0; j < 2; j++) {
            int u = tid + j * 256;
            int row = u >> 3, seg = u & 7;
            int lab = (t == 0) ? 0 : target[row * 30 + t - 1];
            const float* src = emb + lab * 256 + kt + seg * 8;
            float4 a4 = *(const float4*)src;
            float4 b4 = *(const float4*)(src + 4);
            __half2 p0 = __floats2half2_rn(a4.x, a4.y);
            __half2 p1 = __floats2half2_rn(a4.z, a4.w);
            __half2 p2 = __floats2half2_rn(b4.x, b4.y);
            __half2 p3 = __floats2half2_rn(b4.z, b4.w);
            uint4 v = make_uint4(*(unsigned*)&p0, *(unsigned*)&p1,
                                 *(unsigned*)&p2, *(unsigned*)&p3);
            *(uint4*)&As[row * 72 + seg * 8] = v;
        }
#pragma unroll
        for (int j = 0; j < 4; j++) {
            int u = tid + j * 256;
            int row = u >> 4, seg = u & 15;
            *(uint4*)&Bs[row * 136 + seg * 8] =
                *(const uint4*)(g_Wembh + (kt + row) * 2048 + n0 + seg * 8);
        }
        __syncthreads();
#pragma unroll
        for (int kf = 0; kf < 4; kf++) {
            wmma::fragment<wmma::matrix_a, 16, 16, 16, __half, wmma::row_major> af[2];
            wmma::fragment<wmma::matrix_b, 16, 16, 16, __half, wmma::row_major> bf[2];
#pragma unroll
            for (int i = 0; i < 2; i++)
                wmma::load_matrix_sync(af[i], &As[(wm * 32 + i * 16) * 72 + kf * 16], 72);
#pragma unroll
            for (int j = 0; j < 2; j++)
                wmma::load_matrix_sync(bf[j], &Bs[(kf * 16) * 136 + wn * 32 + j * 16], 136);
#pragma unroll
            for (int i = 0; i < 2; i++)
#pragma unroll
                for (int j = 0; j < 2; j++)
                    wmma::mma_sync(acc[i][j], af[i], bf[j], acc[i][j]);
        }
        __syncthreads();
    }
#pragma unroll
    for (int i = 0; i < 2; i++)
#pragma unroll
        for (int j = 0; j < 2; j++)
            wmma::store_matrix_sync(g_pre + (t * 64 + wm * 32 + i * 16) * 2048 + n0 + wn * 32 + j * 16,
                                    acc[i][j], 2048, wmma::mem_row_major);
}

// ---------------- conv v5 ----------------
#define CONV_BUF 27136
__global__ __launch_bounds__(256) void k_conv() {
    extern __shared__ __half csm[];
    const int tid = threadIdx.x;
    const int warp = tid >> 5;
    const int wm = warp >> 1, wn = warp & 1;
    const int n0 = blockIdx.x * 128;
    const int b = blockIdx.y;
    const __half* fTh = g_fmapTh + b * 131072;

    wmma::fragment<wmma::accumulator, 16, 16, 16, float> acc[4][4];
#pragma unroll
    for (int i = 0; i < 4; i++)
#pragma unroll
        for (int j = 0; j < 4; j++) wmma::fill_fragment(acc[i][j], 0.0f);

    auto issue = [&](int q) {
        int tap = q >> 3, cch = q & 7;
        int dy = tap / 3 - 1, dx = tap % 3 - 1;
        __half* A = csm + (q & 1) * CONV_BUF;
        __half* B = A + 18432;
#pragma unroll
        for (int j = 0; j < 8; j++) {
            int u = tid + j * 256;
            int row = u >> 3, seg = u & 7;
            int yy = (row >> 5) + dy, xx = (row & 31) + dx;
            bool ok = (yy >= 0) && (yy < 8) && (xx >= 0) && (xx < 32);
            const __half* src = ok ? (fTh + (yy * 32 + xx) * 512 + cch * 64 + seg * 8) : fTh;
            cp_async16(A + row * 72 + seg * 8, src, ok);
        }
        const __half* bsrc = g_convWH + (tap * 512 + cch * 64) * 256 + n0;
#pragma unroll
        for (int j = 0; j < 4; j++) {
            int u = tid + j * 256;
            int row = u >> 4, c16 = u & 15;
            cp_async16(B + row * 136 + c16 * 8, bsrc + row * 256 + c16 * 8, true);
        }
        asm volatile("cp.async.commit_group;\n" ::: "memory");
    };

    issue(0);
#pragma unroll 1
    for (int q = 0; q < 72; q++) {
        if (q < 71) {
            issue(q + 1);
            asm volatile("cp.async.wait_group 1;\n" ::: "memory");
        } else {
            asm volatile("cp.async.wait_group 0;\n" ::: "memory");
        }
        __syncthreads();
        const __half* A = csm + (q & 1) * CONV_BUF;
        const __half* B = A + 18432;
#pragma unroll
        for (int kf = 0; kf < 4; kf++) {
            wmma::fragment<wmma::matrix_a, 16, 16, 16, __half, wmma::row_major> af[4];
#pragma unroll
            for (int i = 0; i < 4; i++)
                wmma::load_matrix_sync(af[i], &A[(wm * 64 + i * 16) * 72 + kf * 16], 72);
#pragma unroll
            for (int j = 0; j < 4; j++) {
                wmma::fragment<wmma::matrix_b, 16, 16, 16, __half, wmma::row_major> bf;
                wmma::load_matrix_sync(bf, &B[(kf * 16) * 136 + wn * 64 + j * 16], 136);
#pragma unroll
                for (int i = 0; i < 4; i++)
                    wmma::mma_sync(acc[i][j], af[i], bf, acc[i][j]);
            }
        }
        __syncthreads();
    }
    float* eb = g_efmap + b * 65536;
#pragma unroll
    for (int i = 0; i < 4; i++)
#pragma unroll
        for (int j = 0; j < 4; j++)
            wmma::store_matrix_sync(eb + (n0 + wn * 64 + j * 16) * 256 + wm * 64 + i * 16,
                                    acc[i][j], 256, wmma::mem_col_major);
}

// ---------------- persistent recurrence: 512 thr, warp-specialized dual GEMM ----------------
__global__ __launch_bounds__(512)
void k_steps() {
    extern __shared__ char smc[];
    __half* Ah  = (__half*)smc;                                   // 64*1032 halves
    __half* W0s = (__half*)(smc + 132096);                        // 512*24 halves
    __half* W1s = (__half*)(smc + 132096 + 24576);                // 1024*24 halves
    float*  Cs  = (float*)(smc + 132096 + 24576 + 49152);         // 4096 floats
    const int tid = threadIdx.x;
    const int bid = blockIdx.x;
    const int warp = tid >> 5;
    const int n0 = bid * 16;

    for (int j = 0; j < 2; j++) {
        int u = tid + j * 512;
        int k = u >> 1, s = u & 1;
        *(uint4*)&W0s[k * 24 + s * 8] = *(const uint4*)(g_W0h + k * 2048 + n0 + s * 8);
    }
    for (int j = 0; j < 4; j++) {
        int u = tid + j * 512;
        int k = u >> 1, s = u & 1;
        *(uint4*)&W1s[k * 24 + s * 8] = *(const uint4*)(g_W1h + k * 2048 + n0 + s * 8);
    }
    __syncthreads();

    // GEMM role: warps 0-7 -> layer0 (16 mma); warps 8-15 -> layer1 (32 mma)
    const int gw = warp & 7;
    const int mt = gw & 3, kh = gw >> 2;
    const bool isG0 = (warp < 8);

    // pointwise role: tids 0-255 -> layer0; 256-511 -> layer1
    const int s = tid & 255;
    const int pb = s >> 2, pdl = s & 3;
    const int pr = pb & 15, pmt = pb >> 4;
    const int pd = bid * 4 + pdl;
    const bool isP0 = (tid < 256);
    const float4 bi = isP0 ? *(const float4*)&g_b0i[n0 + pdl * 4]
                           : *(const float4*)&g_b1i[n0 + pdl * 4];

#pragma unroll 1
    for (int k = 0; k <= TSTEPS; k++) {
        const int rb = (k + 1) & 1, wb = k & 1;

        {
            const __half* Ag = g_xh[rb];
#pragma unroll
            for (int j = 0; j < 16; j++) {
                int u = tid + j * 512;
                int row = u >> 7, seg = u & 127;
                *(uint4*)&Ah[row * 1032 + seg * 8] =
                    __ldcg((const uint4*)(Ag + row * 1024 + seg * 8));
            }
        }
        // prefetch pointwise operands
        float4 pe = make_float4(0.f, 0.f, 0.f, 0.f);
        float cv = 0.f;
        if (isP0) {
            if (k < TSTEPS) {
                pe = *(const float4*)&g_pre[(k * 64 + pb) * 2048 + n0 + pdl * 4];
                cv = g_c0s[pb * 512 + pd];
            }
        } else {
            if (k > 0) cv = g_c1s[pb * 512 + pd];
        }
        __syncthreads();

        if (isG0) {
            if (k < TSTEPS) {
                wmma::fragment<wmma::accumulator, 16, 16, 16, float> a0, a1;
                wmma::fill_fragment(a0, 0.0f);
                wmma::fill_fragment(a1, 0.0f);
#pragma unroll
                for (int q = 0; q < 16; q++) {
                    int kf = kh * 16 + q;
                    wmma::fragment<wmma::matrix_a, 16, 16, 16, __half, wmma::row_major> af;
                    wmma::fragment<wmma::matrix_b, 16, 16, 16, __half, wmma::row_major> bf;
                    wmma::load_matrix_sync(af, &Ah[(mt * 16) * 1032 + kf * 16], 1032);
                    wmma::load_matrix_sync(bf, &W0s[(kf * 16) * 24], 24);
                    if (q & 1) wmma::mma_sync(a1, af, bf, a1);
                    else       wmma::mma_sync(a0, af, bf, a0);
                }
#pragma unroll
                for (int i = 0; i < a0.num_elements; i++) a0.x[i] += a1.x[i];
                wmma::store_matrix_sync(&Cs[gw * 256], a0, 16, wmma::mem_row_major);
            }
        } else {
            if (k > 0) {
                wmma::fragment<wmma::accumulator, 16, 16, 16, float> a0, a1;
                wmma::fill_fragment(a0, 0.0f);
                wmma::fill_fragment(a1, 0.0f);
#pragma unroll
                for (int q = 0; q < 32; q++) {
                    int kf = kh * 32 + q;
                    wmma::fragment<wmma::matrix_a, 16, 16, 16, __half, wmma::row_major> af;
                    wmma::fragment<wmma::matrix_b, 16, 16, 16, __half, wmma::row_major> bf;
                    wmma::load_matrix_sync(af, &Ah[(mt * 16) * 1032 + kf * 16], 1032);
                    wmma::load_matrix_sync(bf, &W1s[(kf * 16) * 24], 24);
                    if (q & 1) wmma::mma_sync(a1, af, bf, a1);
                    else       wmma::mma_sync(a0, af, bf, a0);
                }
#pragma unroll
                for (int i = 0; i < a0.num_elements; i++) a0.x[i] += a1.x[i];
                wmma::store_matrix_sync(&Cs[2048 + gw * 256], a0, 16, wmma::mem_row_major);
            }
        }
        __syncthreads();

        if (isP0) {
            if (k < TSTEPS) {
                int base = pmt * 256 + pr * 16 + pdl * 4;
                float gi = Cs[base + 0] + Cs[1024 + base + 0] + pe.x + bi.x;
                float gf = Cs[base + 1] + Cs[1024 + base + 1] + pe.y + bi.y;
                float gg = Cs[base + 2] + Cs[1024 + base + 2] + pe.z + bi.z;
                float go = Cs[base + 3] + Cs[1024 + base + 3] + pe.w + bi.w;
                float c = sig_fast(gf) * cv + sig_fast(gi) * tanh_fast(gg);
                float h = sig_fast(go) * tanh_fast(c);
                g_c0s[pb * 512 + pd] = c;
                g_xh[wb][pb * 1024 + pd] = __float2half(h);
            }
        } else {
            if (k > 0) {
                int base = 2048 + pmt * 256 + pr * 16 + pdl * 4;
                float gi = Cs[base + 0] + Cs[1024 + base + 0] + bi.x;
                float gf = Cs[base + 1] + Cs[1024 + base + 1] + bi.y;
                float gg = Cs[base + 2] + Cs[1024 + base + 2] + bi.z;
                float go = Cs[base + 3] + Cs[1024 + base + 3] + bi.w;
                float c = sig_fast(gf) * cv + sig_fast(gi) * tanh_fast(gg);
                float h = sig_fast(go) * tanh_fast(c);
                g_c1s[pb * 512 + pd] = c;
                __half hh = __float2half(h);
                g_xh[wb][pb * 1024 + 512 + pd] = hh;
                g_h1allh[((k - 1) * 64 + pb) * 512 + pd] = hh;
            }
        }
        if (k < TSTEPS) gsync();
    }
}

// ---------------- epilogue: e_h ----------------
__global__ __launch_bounds__(256) void k_eh() {
    __shared__ __half As[64 * 72];
    __shared__ __half Bs[64 * 136];
    const int tid = threadIdx.x;
    const int warp = tid >> 5;
    const int wm = warp >> 2, wn = warp & 3;
    const int n0 = blockIdx.x * 128, m0 = blockIdx.y * 64;
    wmma::fragment<wmma::accumulator, 16, 16, 16, float> acc[2][2];
#pragma unroll
    for (int i = 0; i < 2; i++)
#pragma unroll
        for (int j = 0; j < 2; j++) wmma::fill_fragment(acc[i][j], 0.0f);
    for (int kt = 0; kt < 512; kt += 64) {
#pragma unroll
        for (int j = 0; j < 2; j++) {
            int u = tid + j * 256;
            int row = u >> 3, seg = u & 7;
            *(uint4*)&As[row * 72 + seg * 8] =
                *(const uint4*)(g_h1allh + (m0 + row) * 512 + kt + seg * 8);
        }
#pragma unroll
        for (int j = 0; j < 4; j++) {
            int u = tid + j * 256;
            int row = u >> 4, seg = u & 15;
            *(uint4*)&Bs[row * 136 + seg * 8] =
                *(const uint4*)(g_elwTh + (kt + row) * 256 + n0 + seg * 8);
        }
        __syncthreads();
#pragma unroll
        for (int kf = 0; kf < 4; kf++) {
            wmma::fragment<wmma::matrix_a, 16, 16, 16, __half, wmma::row_major> af[2];
            wmma::fragment<wmma::matrix_b, 16, 16, 16, __half, wmma::row_major> bf[2];
#pragma unroll
            for (int i = 0; i < 2; i++)
                wmma::load_matrix_sync(af[i], &As[(wm * 32 + i * 16) * 72 + kf * 16], 72);
#pragma unroll
            for (int j = 0; j < 2; j++)
                wmma::load_matrix_sync(bf[j], &Bs[(kf * 16) * 136 + wn * 32 + j * 16], 136);
#pragma unroll
            for (int i = 0; i < 2; i++)
#pragma unroll
                for (int j = 0; j < 2; j++)
                    wmma::mma_sync(acc[i][j], af[i], bf[j], acc[i][j]);
        }
        __syncthreads();
    }
#pragma unroll
    for (int i = 0; i < 2; i++)
#pragma unroll
        for (int j = 0; j < 2; j++)
            wmma::store_matrix_sync(g_eh + (m0 + wm * 32 + i * 16) * 256 + n0 + wn * 32 + j * 16,
                                    acc[i][j], 256, wmma::mem_row_major);
}

// ---------------- epilogue: scores + softmax ----------------
__global__ __launch_bounds__(256) void k_scores(const float* __restrict__ elb,
                                                const float* __restrict__ efb,
                                                const float* __restrict__ aw,
                                                const float* __restrict__ ab,
                                                float* __restrict__ out) {
    const int tg = blockIdx.x, b = blockIdx.y;
    const int nt = (tg < 3) ? 8 : 7;
    const int tid = threadIdx.x;
    __shared__ float ehs[8 * 256], aws[256];
    __shared__ float red[8], fin;
    const float bias = elb[tid] + efb[tid];
    for (int j = 0; j < 8; j++)
        ehs[j * 256 + tid] = (j < nt) ? g_eh[((tg * 8 + j) * 64 + b) * 256 + tid] + bias : 0.0f;
    aws[tid] = aw[tid];
    __syncthreads();

    float sc[8];
#pragma unroll
    for (int j = 0; j < 8; j++) sc[j] = ab[0];
    const float* ef = g_efmap + b * 65536 + tid;
#pragma unroll 2
    for (int a = 0; a < 256; a++) {
        float e = ef[a * 256];
        float w = aws[a];
#pragma unroll
        for (int j = 0; j < 8; j++)
            sc[j] += w * tanh_fast(ehs[j * 256 + a] + e);
    }

    const int wp = tid >> 5, lane = tid & 31;
    for (int j = 0; j < nt; j++) {
        float m = sc[j];
#pragma unroll
        for (int o = 16; o; o >>= 1) m = fmaxf(m, __shfl_xor_sync(0xffffffffu, m, o));
        if (lane == 0) red[wp] = m;
        __syncthreads();
        if (tid == 0) {
            float v = red[0];
#pragma unroll
            for (int i = 1; i < 8; i++) v = fmaxf(v, red[i]);
            fin = v;
        }
        __syncthreads();
        float e = expf(sc[j] - fin);
        float ssum = e;
#pragma unroll
        for (int o = 16; o; o >>= 1) ssum += __shfl_xor_sync(0xffffffffu, ssum, o);
        if (lane == 0) red[wp] = ssum;
        __syncthreads();
        if (tid == 0) {
            float v = 0;
#pragma unroll
            for (int i = 0; i < 8; i++) v += red[i];
            fin = v;
        }
        __syncthreads();
        out[194432 + (b * 31 + tg * 8 + j) * 256 + tid] = e / fin;
        __syncthreads();
    }
}

// ---------------- epilogue: glimpse ----------------
__global__ __launch_bounds__(256) void k_glimpse(float* __restrict__ out) {
    __shared__ float ms[16 * 256];
    const int th = blockIdx.x, b = blockIdx.y;
    const int tid = threadIdx.x;
    const int nt = (th == 0) ? 16 : 15;
    for (int i = tid; i < 16 * 256; i += 256) {
        int tt = i >> 8;
        ms[i] = (tt < nt) ? out[194432 + (b * 31 + th * 16 + tt) * 256 + (i & 255)] : 0.0f;
    }
    __syncthreads();
    const int c = tid * 2;
    float2 acc[16];
#pragma unroll
    for (int tt = 0; tt < 16; tt++) acc[tt] = make_float2(0.f, 0.f);
    const float* fp = g_fmapT + b * 131072 + c;
#pragma unroll 4
    for (int hw = 0; hw < 256; hw++) {
        float2 f = *(const float2*)(fp + hw * 512);
#pragma unroll
        for (int tt = 0; tt < 16; tt++) {
            float m = ms[tt * 256 + hw];
            acc[tt].x += f.x * m; acc[tt].y += f.y * m;
        }
    }
#pragma unroll
    for (int tt = 0; tt < 16; tt++)
        if (tt < nt) {
            int row = b * 31 + th * 16 + tt;
            *(float2*)&out[702336 + row * 512 + c] = acc[tt];
            *(__half2*)&g_gh[row * 512 + c] = __floats2half2_rn(acc[tt].x, acc[tt].y);
        }
}

// ---------------- epilogue: fc logits ----------------
__global__ __launch_bounds__(256) void k_fc(const float* __restrict__ fcb,
                                            float* __restrict__ out) {
    __shared__ __half As[64 * 72];
    __shared__ __half Bs[64 * 136];
    __shared__ float Cs[64 * 128];
    const int t = blockIdx.x;
    const int tid = threadIdx.x;
    const int warp = tid >> 5;
    const int wm = warp >> 2, wn = warp & 3;
    wmma::fragment<wmma::accumulator, 16, 16, 16, float> acc[2][2];
#pragma unroll
    for (int i = 0; i < 2; i++)
#pragma unroll
        for (int j = 0; j < 2; j++) wmma::fill_fragment(acc[i][j], 0.0f);
    for (int kt = 0; kt < 1024; kt += 64) {
#pragma unroll
        for (int j = 0; j < 2; j++) {
            int u = tid + j * 256;
            int row = u >> 3, seg = u & 7;
            const __half* src = (kt < 512)
                ? (g_h1allh + (t * 64 + row) * 512 + kt + seg * 8)
                : (g_gh + (row * 31 + t) * 512 + (kt - 512) + seg * 8);
            *(uint4*)&As[row * 72 + seg * 8] = *(const uint4*)src;
        }
#pragma unroll
        for (int j = 0; j < 4; j++) {
            int u = tid + j * 256;
            int row = u >> 4, seg = u & 15;
            *(uint4*)&Bs[row * 136 + seg * 8] =
                *(const uint4*)(g_fcTph + (kt + row) * 128 + seg * 8);
        }
        __syncthreads();
#pragma unroll
        for (int kf = 0; kf < 4; kf++) {
            wmma::fragment<wmma::matrix_a, 16, 16, 16, __half, wmma::row_major> af[2];
            wmma::fragment<wmma::matrix_b, 16, 16, 16, __half, wmma::row_major> bf[2];
#pragma unroll
            for (int i = 0; i < 2; i++)
                wmma::load_matrix_sync(af[i], &As[(wm * 32 + i * 16) * 72 + kf * 16], 72);
#pragma unroll
            for (int j = 0; j < 2; j++)
                wmma::load_matrix_sync(bf[j], &Bs[(kf * 16) * 136 + wn * 32 + j * 16], 136);
#pragma unroll
            for (int i = 0; i < 2; i++)
#pragma unroll
                for (int j = 0; j < 2; j++)
                    wmma::mma_sync(acc[i][j], af[i], bf[j], acc[i][j]);
        }
        __syncthreads();
    }
#pragma unroll
    for (int i = 0; i < 2; i++)
#pragma unroll
        for (int j = 0; j < 2; j++)
            wmma::store_matrix_sync(&Cs[(wm * 32 + i * 16) * 128 + wn * 32 + j * 16],
                                    acc[i][j], 128, wmma::mem_row_major);
    __syncthreads();
    for (int i = tid; i < 64 * 98; i += 256) {
        int m = i / 98, j = i % 98;
        out[(m * 31 + t) * 98 + j] = Cs[m * 128 + j] + fcb[j];
    }
}

// ---------------- launch ----------------
extern "C" void kernel_launch(void* const* d_in, const int* in_sizes, int n_in,
                              void* d_out, int out_size) {
    const float* fmap   = (const float*)d_in[0];
    const float* h0     = (const float*)d_in[1];
    const float* c0     = (const float*)d_in[2];
    const int*   target = (const int*)d_in[3];
    const float* emb    = (const float*)d_in[5];
    const float* Wih0   = (const float*)d_in[6];
    const float* Whh0   = (const float*)d_in[7];
    const float* bih0   = (const float*)d_in[8];
    const float* bhh0   = (const float*)d_in[9];
    const float* Wih1   = (const float*)d_in[10];
    const float* Whh1   = (const float*)d_in[11];
    const float* bih1   = (const float*)d_in[12];
    const float* bhh1   = (const float*)d_in[13];
    const float* elw    = (const float*)d_in[14];
    const float* elb    = (const float*)d_in[15];
    const float* efw    = (const float*)d_in[16];
    const float* efb    = (const float*)d_in[17];
    const float* aw     = (const float*)d_in[18];
    const float* ab     = (const float*)d_in[19];
    const float* fcw    = (const float*)d_in[20];
    const float* fcb    = (const float*)d_in[21];
    float* out = (float*)d_out;

    const int SMEM_STEPS = 132096 + 24576 + 49152 + 16384;  // 222208
    const int SMEM_CONV  = 2 * CONV_BUF * 2;                // 108544

    static cudaStream_t s2 = nullptr;
    static cudaEvent_t evRoot = nullptr, evConv = nullptr;
    if (!s2) {
        cudaFuncSetAttribute(k_steps, cudaFuncAttributeMaxDynamicSharedMemorySize, SMEM_STEPS);
        cudaFuncSetAttribute(k_conv, cudaFuncAttributeMaxDynamicSharedMemorySize, SMEM_CONV);
        cudaStreamCreateWithFlags(&s2, cudaStreamNonBlocking);
        cudaEventCreateWithFlags(&evRoot, cudaEventDisableTiming);
        cudaEventCreateWithFlags(&evConv, cudaEventDisableTiming);
    }

    cudaEventRecord(evRoot, 0);
    cudaStreamWaitEvent(s2, evRoot, 0);
    k_fmapT<<<dim3(128, 64), 256, 0, s2>>>(fmap);
    k_ctrans<<<dim3(8, 16), 256, 0, s2>>>(efw);
    k_conv<<<dim3(2, 64), 256, SMEM_CONV, s2>>>();
    cudaEventRecord(evConv, s2);

    k_wtrans<<<dim3(2048, 4), 256>>>(Whh0, Wih1, Whh1, Wih0, elw, fcw,
                                     bih0, bhh0, bih1, bhh1);
    k_init2<<<512, 256>>>(h0, c0);
    k_preemb<<<dim3(16, 31), 256>>>(emb, target);
    k_steps<<<GBLK, 512, SMEM_STEPS>>>();
    k_eh<<<dim3(2, 31), 256>>>();

    cudaStreamWaitEvent(0, evConv, 0);
    k_scores<<<dim3(4, 64), 256>>>(elb, efb, aw, ab, out);
    k_glimpse<<<dim3(2, 64), 256>>>(out);
    k_fc<<<31, 256>>>(fcb, out);
}